// round 10
// baseline (speedup 1.0000x reference)
#include <cuda_runtime.h>
#include <cuda_fp16.h>
#include <math.h>
#include <stdint.h>

#define D       128
#define NHEADS  4
#define MAXN    50048
#define MAXE    640000
#define MAXR    256
#define LAYERS  2

// fp16 dual GEMM v3: CTA tile M=64, N=256. B resident in smem; A fragments direct LDG from xh.
#define DSTR 68
#define DB_WORDS (256*DSTR)                   // 17408
#define DB_SMEM  (DB_WORDS*4)                 // 69632 -> 3 CTAs/SM

// fp16 proj GEMM: CTA tile M=64, N=128, K=320 in 5 chunks of 64
#define PSTR 36
#define PM_A_WORDS (2*64*PSTR)
#define PM_B_WORDS (2*128*PSTR)
#define PM_SMEM ((PM_A_WORDS + PM_B_WORDS)*4) // 55296

// ---------------- helpers ----------------
__device__ __forceinline__ void cp_async16(unsigned saddr, const void* gaddr, int valid) {
    asm volatile("cp.async.ca.shared.global [%0], [%1], 16, %2;"
                 :: "r"(saddr), "l"(gaddr), "r"(valid ? 16 : 0));
}
__device__ __forceinline__ void cp_commit() { asm volatile("cp.async.commit_group;"); }
__device__ __forceinline__ void cp_wait0()  { asm volatile("cp.async.wait_group 0;"); }

__device__ __forceinline__ float4 ldnc4(const float* p) {
    float4 v;
    asm volatile("ld.global.nc.L1::no_allocate.v4.f32 {%0,%1,%2,%3}, [%4];"
                 : "=f"(v.x), "=f"(v.y), "=f"(v.z), "=f"(v.w) : "l"(p));
    return v;
}

__device__ __forceinline__ uint32_t f2h2(float lo, float hi) {
    __half2 h = __floats2half2_rn(lo, hi);
    return *(uint32_t*)&h;
}

// m16n8k16 fp16 MMA, fp32 accumulate
__device__ __forceinline__ void mma_f16(float* d, const uint32_t* a, uint32_t b0, uint32_t b1) {
    asm volatile(
        "mma.sync.aligned.m16n8k16.row.col.f32.f16.f16.f32 "
        "{%0,%1,%2,%3}, {%4,%5,%6,%7}, {%8,%9}, {%0,%1,%2,%3};"
        : "+f"(d[0]), "+f"(d[1]), "+f"(d[2]), "+f"(d[3])
        : "r"(a[0]), "r"(a[1]), "r"(a[2]), "r"(a[3]), "r"(b0), "r"(b1));
}

// ---------------- device scratch ----------------
__device__ float    g_xl[MAXN*D];
__device__ float    g_xr[MAXN*D];
__device__ uint32_t g_xh[MAXN*64];            // fp16 x image [n][64 half2-words]
__device__ int      g_rowptr[MAXN+1];
__device__ int      g_woff[MAXN];
__device__ int      g_adj[MAXE];
__device__ int      g_partials[128];
__device__ float    g_relproj[LAYERS*MAXR*D];
__device__ uint32_t g_bstage[LAYERS*256*64];  // fp16 dual-B images [n=256][kw=64]
__device__ uint32_t g_bproj[128*160];         // fp16 proj-B image  [n=128][kw=160]

// ---------------- CSR build ----------------
__global__ void hist_kernel(const int* __restrict__ dst, int* cnt, int e) {
    int i = blockIdx.x*blockDim.x + threadIdx.x;
    if (i < e) atomicAdd(&cnt[dst[i]], 1);
}

__global__ void scan1_kernel(const int* __restrict__ cnt, int* rowptr, int* partials, int n) {
    __shared__ int sh[1024];
    int i = blockIdx.x*1024 + threadIdx.x;
    int v = (i < n) ? cnt[i] : 0;
    sh[threadIdx.x] = v;
    __syncthreads();
    for (int off = 1; off < 1024; off <<= 1) {
        int t = (threadIdx.x >= off) ? sh[threadIdx.x - off] : 0;
        __syncthreads();
        sh[threadIdx.x] += t;
        __syncthreads();
    }
    if (i < n) rowptr[i] = sh[threadIdx.x] - v;
    if (threadIdx.x == 1023) partials[blockIdx.x] = sh[1023];
}

__global__ void scan2_kernel(int* partials, int* rowptr, int nb, int n, int total) {
    __shared__ int sh[128];
    int v = (threadIdx.x < nb) ? partials[threadIdx.x] : 0;
    sh[threadIdx.x] = v;
    __syncthreads();
    for (int off = 1; off < 128; off <<= 1) {
        int t = (threadIdx.x >= off) ? sh[threadIdx.x - off] : 0;
        __syncthreads();
        sh[threadIdx.x] += t;
        __syncthreads();
    }
    if (threadIdx.x < nb) partials[threadIdx.x] = sh[threadIdx.x] - v;
    if (threadIdx.x == 0) rowptr[n] = total;
}

__global__ void scan3_kernel(int* rowptr, const int* __restrict__ partials, int* woff, int n) {
    int i = blockIdx.x*blockDim.x + threadIdx.x;
    if (i < n) {
        int v = rowptr[i] + partials[i >> 10];
        rowptr[i] = v;
        woff[i] = v;
    }
}

__global__ void scatter_kernel(const int* __restrict__ src, const int* __restrict__ dst,
                               const int* __restrict__ etype, int* woff, int* adj, int e) {
    int i = blockIdx.x*blockDim.x + threadIdx.x;
    if (i < e) {
        int p = atomicAdd(&woff[dst[i]], 1);
        adj[p] = src[i] | (etype[i] << 20);
    }
}

// ---------------- rel_proj: 4 relations per block, 4-way ILP ----------------
__global__ void relproj_kernel(const float* __restrict__ rel, const float* __restrict__ we,
                               float* __restrict__ outp, int Rn) {
    int r0 = blockIdx.x * 4, l = blockIdx.y, c = threadIdx.x;
    __shared__ float sr[4][D];
#pragma unroll
    for (int j = 0; j < 4; j++) {
        int rr = r0 + j;
        sr[j][c] = (rr < Rn) ? rel[rr*D + c] : 0.f;
    }
    __syncthreads();
    const float* W = we + l*D*D;
    float a0 = 0.f, a1 = 0.f, a2 = 0.f, a3 = 0.f;
#pragma unroll 16
    for (int k = 0; k < D; k++) {
        float w = __ldg(&W[k*D + c]);
        a0 = fmaf(sr[0][k], w, a0);
        a1 = fmaf(sr[1][k], w, a1);
        a2 = fmaf(sr[2][k], w, a2);
        a3 = fmaf(sr[3][k], w, a3);
    }
    if (r0 + 0 < Rn) outp[(l*Rn + r0 + 0)*D + c] = a0;
    if (r0 + 1 < Rn) outp[(l*Rn + r0 + 1)*D + c] = a1;
    if (r0 + 2 < Rn) outp[(l*Rn + r0 + 2)*D + c] = a2;
    if (r0 + 3 < Rn) outp[(l*Rn + r0 + 3)*D + c] = a3;
}

// ---------------- B pre-stages (fp16 pairs) ----------------
__global__ void prep_b_kernel(const float* __restrict__ wl, const float* __restrict__ wr,
                              uint32_t* __restrict__ gB) {
    int nrow = blockIdx.x, l = blockIdx.y, kw = threadIdx.x;   // kw 0..63
    int c = nrow & 127;
    const float* W = (nrow < 128) ? (wl + l*D*D) : (wr + l*D*D);
    gB[l*16384 + nrow*64 + kw] = f2h2(W[(2*kw)*D + c], W[(2*kw+1)*D + c]);
}

__global__ void prep_bp_kernel(const float* __restrict__ pw, uint32_t* __restrict__ gBp, int F) {
    int nrow = blockIdx.x;        // 0..127
    int kw = threadIdx.x;         // 0..159
    float v0 = (2*kw     < F) ? pw[(2*kw)*128 + nrow]     : 0.f;
    float v1 = (2*kw + 1 < F) ? pw[(2*kw + 1)*128 + nrow] : 0.f;
    gBp[nrow*160 + kw] = f2h2(v0, v1);
}

// ---------------- fp16 proj GEMM -> writes fp16 x image ----------------
__global__ __launch_bounds__(256, 2) void proj_mma_kernel(
    const float* __restrict__ nf, const int* __restrict__ entity,
    const uint32_t* __restrict__ gBp, const float* __restrict__ pb,
    uint32_t* __restrict__ xh, int n, int F, int nTiles) {
    extern __shared__ uint32_t smu[];
    uint32_t* AsU = smu;                 // [2][64][PSTR]
    uint32_t* BsU = smu + PM_A_WORDS;    // [2][128][PSTR]
    int tid = threadIdx.x, lane = tid & 31, wid = tid >> 5;
    int wm = wid >> 2, wn = wid & 3;
    int lr = lane >> 2, lc = lane & 3;

    unsigned bbase = (unsigned)__cvta_generic_to_shared(BsU);

    float bjx[4], bjy[4];
#pragma unroll
    for (int nt = 0; nt < 4; nt++) {
        int col = wn*32 + nt*8 + 2*lc;
        bjx[nt] = pb[col];
        bjy[nt] = pb[col+1];
    }

    float4 aReg[4];
    auto loadA = [&](int t, int c) {
#pragma unroll
        for (int j = 0; j < 4; j++) {
            int q = tid + j*256;
            int r = q >> 4, k4 = q & 15;
            int gr = t*64 + r;
            int kg = c*64 + k4*4;
            aReg[j] = (gr < n && kg < F)
                ? *(const float4*)&nf[(long long)entity[gr]*F + kg]
                : make_float4(0,0,0,0);
        }
    };
    auto stsA = [&](int buf) {
#pragma unroll
        for (int j = 0; j < 4; j++) {
            int q = tid + j*256;
            int r = q >> 4, k4 = q & 15;
            uint2 w = make_uint2(f2h2(aReg[j].x, aReg[j].y), f2h2(aReg[j].z, aReg[j].w));
            *(uint2*)&AsU[buf*64*PSTR + r*PSTR + k4*2] = w;
        }
    };
    auto issueB = [&](int c, int buf) {
#pragma unroll
        for (int j = 0; j < 4; j++) {
            int q = tid + j*256;
            int row = q >> 3, seg = q & 7;
            cp_async16(bbase + (buf*128*PSTR + row*PSTR + seg*4)*4,
                       gBp + row*160 + c*32 + seg*4, 1);
        }
        cp_commit();
    };

    int tile0 = blockIdx.x;
    loadA(tile0, 0);
    issueB(0, 0);
    stsA(0);
    cp_wait0();
    __syncthreads();

    int buf = 0;
    for (int t = tile0; t < nTiles; t += gridDim.x) {
        float acc[2][4][4];
#pragma unroll
        for (int mt = 0; mt < 2; mt++)
#pragma unroll
            for (int nt = 0; nt < 4; nt++)
#pragma unroll
                for (int i = 0; i < 4; i++) acc[mt][nt][i] = 0.f;

#pragma unroll
        for (int c = 0; c < 5; c++) {
            int tn = (c < 4) ? t : t + gridDim.x;
            int cn = (c < 4) ? c + 1 : 0;
            bool hasNext = (c < 4) || (tn < nTiles);
            if (hasNext) { loadA(tn, cn); issueB(cn, buf ^ 1); }

            const uint32_t* Ab = &AsU[buf*64*PSTR];
            const uint32_t* Bb = &BsU[buf*128*PSTR];
#pragma unroll
            for (int kk = 0; kk < 4; kk++) {
                int kw0 = kk*8;
                uint32_t a[2][4];
#pragma unroll
                for (int mt = 0; mt < 2; mt++) {
                    int r = wm*32 + mt*16 + lr;
                    a[mt][0] = Ab[r*PSTR + kw0 + lc];
                    a[mt][1] = Ab[(r+8)*PSTR + kw0 + lc];
                    a[mt][2] = Ab[r*PSTR + kw0 + lc + 4];
                    a[mt][3] = Ab[(r+8)*PSTR + kw0 + lc + 4];
                }
#pragma unroll
                for (int nt = 0; nt < 4; nt++) {
                    int nrow = wn*32 + nt*8 + lr;
                    uint32_t b0 = Bb[nrow*PSTR + kw0 + lc];
                    uint32_t b1 = Bb[nrow*PSTR + kw0 + lc + 4];
                    mma_f16(acc[0][nt], a[0], b0, b1);
                    mma_f16(acc[1][nt], a[1], b0, b1);
                }
            }

            if (c == 4) {
#pragma unroll
                for (int mt = 0; mt < 2; mt++) {
                    int r1 = t*64 + wm*32 + mt*16 + lr;
#pragma unroll
                    for (int nt = 0; nt < 4; nt++) {
                        int col = wn*32 + nt*8 + 2*lc;
                        if (r1 < n)
                            xh[(size_t)r1*64 + (col>>1)] =
                                f2h2(acc[mt][nt][0] + bjx[nt], acc[mt][nt][1] + bjy[nt]);
                        if (r1 + 8 < n)
                            xh[(size_t)(r1+8)*64 + (col>>1)] =
                                f2h2(acc[mt][nt][2] + bjx[nt], acc[mt][nt][3] + bjy[nt]);
                    }
                }
            }

            if (hasNext) stsA(buf ^ 1);
            cp_wait0();
            __syncthreads();
            buf ^= 1;
        }
    }
}

// ---------------- fp16 dual GEMM v3: B in smem, A fragments via direct LDG ----------------
__global__ __launch_bounds__(256, 3) void gemm_dual_mma_kernel(
    const uint32_t* __restrict__ xh, const uint32_t* __restrict__ gB,
    const float* __restrict__ bl, const float* __restrict__ br,
    float* __restrict__ outl, float* __restrict__ outr, int n, int nTiles) {
    extern __shared__ uint32_t BsU[];          // [256][DSTR]
    int tid = threadIdx.x, lane = tid & 31, wid = tid >> 5;
    int wm = wid >> 2, wn = wid & 3;
    int lr = lane >> 2, lc = lane & 3;

    // B: whole [256][64w] fp16 image once per CTA
    {
        unsigned bbase = (unsigned)__cvta_generic_to_shared(BsU);
#pragma unroll
        for (int j = 0; j < 16; j++) {
            int q = tid + j*256;
            int row = q >> 4, seg = q & 15;
            cp_async16(bbase + (row*DSTR + seg*4)*4, gB + row*64 + seg*4, 1);
        }
        cp_commit();
        cp_wait0();
    }
    __syncthreads();

    for (int t = blockIdx.x; t < nTiles; t += gridDim.x) {
        float acc[2][8][4];
#pragma unroll
        for (int mt = 0; mt < 2; mt++)
#pragma unroll
            for (int nt = 0; nt < 8; nt++)
#pragma unroll
                for (int i = 0; i < 4; i++) acc[mt][nt][i] = 0.f;

        int rbase = t*64 + wm*32 + lr;
        const uint32_t* A0 = xh + (size_t)rbase*64;
        const uint32_t* A1 = xh + (size_t)(rbase + 16)*64;

#pragma unroll
        for (int kk = 0; kk < 8; kk++) {
            int kw0 = kk*8;
            uint32_t a[2][4];
            a[0][0] = __ldg(&A0[kw0 + lc]);
            a[0][1] = __ldg(&A0[8*64 + kw0 + lc]);
            a[0][2] = __ldg(&A0[kw0 + lc + 4]);
            a[0][3] = __ldg(&A0[8*64 + kw0 + lc + 4]);
            a[1][0] = __ldg(&A1[kw0 + lc]);
            a[1][1] = __ldg(&A1[8*64 + kw0 + lc]);
            a[1][2] = __ldg(&A1[kw0 + lc + 4]);
            a[1][3] = __ldg(&A1[8*64 + kw0 + lc + 4]);
#pragma unroll
            for (int nt = 0; nt < 8; nt++) {
                int nrow = wn*64 + nt*8 + lr;
                uint32_t b0 = BsU[nrow*DSTR + kw0 + lc];
                uint32_t b1 = BsU[nrow*DSTR + kw0 + lc + 4];
                mma_f16(acc[0][nt], a[0], b0, b1);
                mma_f16(acc[1][nt], a[1], b0, b1);
            }
        }

#pragma unroll
        for (int mt = 0; mt < 2; mt++) {
            int r1 = t*64 + wm*32 + mt*16 + lr;
#pragma unroll
            for (int nt = 0; nt < 8; nt++) {
                int col = wn*64 + nt*8 + 2*lc;
                float* op = (col < 128) ? outl : outr;
                const float* bv = (col < 128) ? bl : br;
                int c = col & 127;
                float bx = __ldg(&bv[c]), by = __ldg(&bv[c+1]);
                if (r1 < n)
                    *(float2*)&op[r1*128 + c] =
                        make_float2(acc[mt][nt][0] + bx, acc[mt][nt][1] + by);
                if (r1 + 8 < n)
                    *(float2*)&op[(r1+8)*128 + c] =
                        make_float2(acc[mt][nt][2] + bx, acc[mt][nt][3] + by);
            }
        }
    }
}

// ---------------- fused GATv2 attention + softmax + aggregation ----------------
__global__ __launch_bounds__(256) void gat_agg_kernel(
    const float* __restrict__ xl, const float* __restrict__ xr,
    const int* __restrict__ rowptr, const int* __restrict__ adj,
    const float* __restrict__ relproj, const float* __restrict__ att,
    const float* __restrict__ bias, float* __restrict__ out,
    uint32_t* __restrict__ xh, int n, int do_elu) {
    int warp = (blockIdx.x*blockDim.x + threadIdx.x) >> 5;
    if (warp >= n) return;
    int lane = threadIdx.x & 31;
    int c0 = lane * 4;

    const float4 attv = *(const float4*)&att[c0];
    const float4 xrv  = *(const float4*)&xr[warp*D + c0];
    float4 acc = make_float4(0.f, 0.f, 0.f, 0.f);
    float s = 0.f;

    int e0 = rowptr[warp], e1 = rowptr[warp+1];
    int e = e0;
    for (; e + 4 <= e1; e += 4) {
        int p[4];
        float4 xv[4], rv[4];
#pragma unroll
        for (int i = 0; i < 4; i++) p[i] = __ldg(&adj[e+i]);
#pragma unroll
        for (int i = 0; i < 4; i++) {
            xv[i] = ldnc4(&xl[(p[i] & 0xFFFFF)*D + c0]);
            rv[i] = *(const float4*)&relproj[(p[i] >> 20)*D + c0];
        }
        float d[4];
#pragma unroll
        for (int i = 0; i < 4; i++) {
            float m0 = xv[i].x + xrv.x + rv[i].x;
            float m1 = xv[i].y + xrv.y + rv[i].y;
            float m2 = xv[i].z + xrv.z + rv[i].z;
            float m3 = xv[i].w + xrv.w + rv[i].w;
            float dd =        fmaf(0.4f, fabsf(m0), 0.6f*m0) * attv.x;
            dd = fmaf(fmaf(0.4f, fabsf(m1), 0.6f*m1), attv.y, dd);
            dd = fmaf(fmaf(0.4f, fabsf(m2), 0.6f*m2), attv.z, dd);
            dd = fmaf(fmaf(0.4f, fabsf(m3), 0.6f*m3), attv.w, dd);
            d[i] = dd;
        }
#pragma unroll
        for (int i = 0; i < 4; i++) d[i] += __shfl_xor_sync(0xffffffffu, d[i], 1);
#pragma unroll
        for (int i = 0; i < 4; i++) d[i] += __shfl_xor_sync(0xffffffffu, d[i], 2);
#pragma unroll
        for (int i = 0; i < 4; i++) d[i] += __shfl_xor_sync(0xffffffffu, d[i], 4);

        float w0 = __expf(d[0]), w1 = __expf(d[1]);
        float w2 = __expf(d[2]), w3 = __expf(d[3]);
        s += (w0 + w1) + (w2 + w3);
        acc.x += fmaf(w0, xv[0].x, w1*xv[1].x) + fmaf(w2, xv[2].x, w3*xv[3].x);
        acc.y += fmaf(w0, xv[0].y, w1*xv[1].y) + fmaf(w2, xv[2].y, w3*xv[3].y);
        acc.z += fmaf(w0, xv[0].z, w1*xv[1].z) + fmaf(w2, xv[2].z, w3*xv[3].z);
        acc.w += fmaf(w0, xv[0].w, w1*xv[1].w) + fmaf(w2, xv[2].w, w3*xv[3].w);
    }
    for (; e < e1; e++) {
        int p0 = __ldg(&adj[e]);
        float4 x0 = ldnc4(&xl[(p0 & 0xFFFFF)*D + c0]);
        float4 r0 = *(const float4*)&relproj[(p0 >> 20)*D + c0];
        float m0 = x0.x + xrv.x + r0.x, m1 = x0.y + xrv.y + r0.y;
        float m2 = x0.z + xrv.z + r0.z, m3 = x0.w + xrv.w + r0.w;
        float d0 =        fmaf(0.4f, fabsf(m0), 0.6f*m0) * attv.x;
        d0 = fmaf(fmaf(0.4f, fabsf(m1), 0.6f*m1), attv.y, d0);
        d0 = fmaf(fmaf(0.4f, fabsf(m2), 0.6f*m2), attv.z, d0);
        d0 = fmaf(fmaf(0.4f, fabsf(m3), 0.6f*m3), attv.w, d0);
        d0 += __shfl_xor_sync(0xffffffffu, d0, 1);
        d0 += __shfl_xor_sync(0xffffffffu, d0, 2);
        d0 += __shfl_xor_sync(0xffffffffu, d0, 4);
        float w0 = __expf(d0);
        s += w0;
        acc.x = fmaf(w0, x0.x, acc.x);
        acc.y = fmaf(w0, x0.y, acc.y);
        acc.z = fmaf(w0, x0.z, acc.z);
        acc.w = fmaf(w0, x0.w, acc.w);
    }

    float inv = (s > 0.f) ? (1.f / s) : 0.f;
    float4 bj = *(const float4*)&bias[c0];
    float4 r;
    r.x = fmaf(acc.x, inv, bj.x);
    r.y = fmaf(acc.y, inv, bj.y);
    r.z = fmaf(acc.z, inv, bj.z);
    r.w = fmaf(acc.w, inv, bj.w);
    if (do_elu) {
        r.x = (r.x > 0.f) ? r.x : (__expf(r.x) - 1.f);
        r.y = (r.y > 0.f) ? r.y : (__expf(r.y) - 1.f);
        r.z = (r.z > 0.f) ? r.z : (__expf(r.z) - 1.f);
        r.w = (r.w > 0.f) ? r.w : (__expf(r.w) - 1.f);
    }
    if (xh) {
        uint2 w = make_uint2(f2h2(r.x, r.y), f2h2(r.z, r.w));
        *(uint2*)&xh[(size_t)warp*64 + lane*2] = w;
    } else {
        *(float4*)&out[warp*D + c0] = r;
    }
}

// ---------------- launch ----------------
extern "C" void kernel_launch(void* const* d_in, const int* in_sizes, int n_in,
                              void* d_out, int out_size) {
    const int*   entity = (const int*)  d_in[0];
    const int*   eidx   = (const int*)  d_in[1];
    const int*   etype  = (const int*)  d_in[2];
    const float* nf     = (const float*)d_in[3];
    const float* rel    = (const float*)d_in[4];
    const float* pw     = (const float*)d_in[5];
    const float* pb     = (const float*)d_in[6];
    const float* wl     = (const float*)d_in[7];
    const float* bl     = (const float*)d_in[8];
    const float* wr     = (const float*)d_in[9];
    const float* brr    = (const float*)d_in[10];
    const float* we     = (const float*)d_in[11];
    const float* att    = (const float*)d_in[12];
    const float* bias   = (const float*)d_in[13];
    float* out = (float*)d_out;

    int n  = in_sizes[0];
    int e  = in_sizes[2];
    int Rn = in_sizes[4] / D;
    int F  = in_sizes[3] / n;
    const int* srcp = eidx;
    const int* dstp = eidx + e;

    float *pxl, *pxr, *prelp;
    uint32_t *pbst, *pbpj, *pxh;
    int *prow, *pwoff, *padj, *ppart;
    cudaGetSymbolAddress((void**)&pxl,   g_xl);
    cudaGetSymbolAddress((void**)&pxr,   g_xr);
    cudaGetSymbolAddress((void**)&pxh,   g_xh);
    cudaGetSymbolAddress((void**)&prelp, g_relproj);
    cudaGetSymbolAddress((void**)&pbst,  g_bstage);
    cudaGetSymbolAddress((void**)&pbpj,  g_bproj);
    cudaGetSymbolAddress((void**)&prow,  g_rowptr);
    cudaGetSymbolAddress((void**)&pwoff, g_woff);
    cudaGetSymbolAddress((void**)&padj,  g_adj);
    cudaGetSymbolAddress((void**)&ppart, g_partials);

    int nsm = 148;
    cudaDeviceGetAttribute(&nsm, cudaDevAttrMultiProcessorCount, 0);

    cudaFuncSetAttribute(proj_mma_kernel, cudaFuncAttributeMaxDynamicSharedMemorySize, PM_SMEM);
    cudaFuncSetAttribute(gemm_dual_mma_kernel, cudaFuncAttributeMaxDynamicSharedMemorySize, DB_SMEM);

    // side stream for CSR build (created once, outside any capture; fork/join via events)
    static cudaStream_t s2 = nullptr;
    static cudaEvent_t evF = nullptr, evJ = nullptr;
    if (s2 == nullptr) {
        cudaStreamCreateWithFlags(&s2, cudaStreamNonBlocking);
        cudaEventCreateWithFlags(&evF, cudaEventDisableTiming);
        cudaEventCreateWithFlags(&evJ, cudaEventDisableTiming);
    }

    int nTiles = (n + 63) / 64;
    int projGrid = (nTiles < 2*nsm) ? nTiles : 2*nsm;
    int dualGrid = (nTiles < 3*nsm) ? nTiles : 3*nsm;
    int aggBlocks = (n*32 + 255) / 256;
    int nb = (n + 1023) / 1024;

    // fork: CSR build + relproj on s2, GEMM chain on main stream
    cudaEventRecord(evF, 0);
    cudaStreamWaitEvent(s2, evF, 0);

    cudaMemsetAsync(pwoff, 0, (size_t)n * sizeof(int), s2);
    hist_kernel<<<(e+255)/256, 256, 0, s2>>>(dstp, pwoff, e);
    scan1_kernel<<<nb, 1024, 0, s2>>>(pwoff, prow, ppart, n);
    scan2_kernel<<<1, 128, 0, s2>>>(ppart, prow, nb, n, e);
    scan3_kernel<<<(n+255)/256, 256, 0, s2>>>(prow, ppart, pwoff, n);
    scatter_kernel<<<(e+255)/256, 256, 0, s2>>>(srcp, dstp, etype, pwoff, padj, e);
    relproj_kernel<<<dim3((Rn + 3)/4, LAYERS), D, 0, s2>>>(rel, we, prelp, Rn);
    cudaEventRecord(evJ, s2);

    // main stream: GEMM chain
    prep_bp_kernel<<<128, 160>>>(pw, pbpj, F);
    prep_b_kernel<<<dim3(256, LAYERS), 64>>>(wl, wr, pbst);
    proj_mma_kernel<<<projGrid, 256, PM_SMEM>>>(nf, entity, pbpj, pb, pxh, n, F, nTiles);
    gemm_dual_mma_kernel<<<dualGrid, 256, DB_SMEM>>>(pxh, pbst, bl, brr,
                                                     pxl, pxr, n, nTiles);

    // join: agg needs CSR + relproj
    cudaStreamWaitEvent(0, evJ, 0);

    // layer 0 aggregation -> fp16 x image (feeds dual L1)
    gat_agg_kernel<<<aggBlocks, 256>>>(pxl, pxr, prow, padj, prelp, att, bias,
                                       out, pxh, n, 1);

    // layer 1
    gemm_dual_mma_kernel<<<dualGrid, 256, DB_SMEM>>>(pxh, pbst + 16384, bl + D, brr + D,
                                                     pxl, pxr, n, nTiles);
    gat_agg_kernel<<<aggBlocks, 256>>>(pxl, pxr, prow, padj, prelp + Rn*D, att + D, bias + D,
                                       out, (uint32_t*)nullptr, n, 0);
}

// round 11
// speedup vs baseline: 1.1585x; 1.1585x over previous
#include <cuda_runtime.h>
#include <cuda_fp16.h>
#include <math.h>
#include <stdint.h>

#define D       128
#define NHEADS  4
#define MAXN    50048
#define MAXE    640000
#define MAXR    256
#define LAYERS  2

// fp16 dual GEMM (round-9 config): CTA tile M=64, N=256, A via cp.async from fp16 x image.
#define DSTR 68
#define DA_WORDS (2*64*DSTR)                  // 8704
#define DB_WORDS (256*DSTR)                   // 17408
#define MMA_SMEM ((DA_WORDS + DB_WORDS)*4)    // 104448 -> 2 CTAs/SM

// fp16 proj GEMM: CTA tile M=64, N=128, K=320 in 5 chunks of 64
#define PSTR 36
#define PM_A_WORDS (2*64*PSTR)
#define PM_B_WORDS (2*128*PSTR)
#define PM_SMEM ((PM_A_WORDS + PM_B_WORDS)*4) // 55296

// ---------------- helpers ----------------
__device__ __forceinline__ void cp_async16(unsigned saddr, const void* gaddr, int valid) {
    asm volatile("cp.async.ca.shared.global [%0], [%1], 16, %2;"
                 :: "r"(saddr), "l"(gaddr), "r"(valid ? 16 : 0));
}
__device__ __forceinline__ void cp_commit() { asm volatile("cp.async.commit_group;"); }
__device__ __forceinline__ void cp_wait0()  { asm volatile("cp.async.wait_group 0;"); }

// non-allocating L1 8B load (for xl fp16 gathers)
__device__ __forceinline__ uint2 ldnc2u(const uint32_t* p) {
    uint2 v;
    asm volatile("ld.global.nc.L1::no_allocate.v2.u32 {%0,%1}, [%2];"
                 : "=r"(v.x), "=r"(v.y) : "l"(p));
    return v;
}

__device__ __forceinline__ uint32_t f2h2(float lo, float hi) {
    __half2 h = __floats2half2_rn(lo, hi);
    return *(uint32_t*)&h;
}
__device__ __forceinline__ float2 h22f2(uint32_t w) {
    return __half22float2(*(__half2*)&w);
}

// m16n8k16 fp16 MMA, fp32 accumulate
__device__ __forceinline__ void mma_f16(float* d, const uint32_t* a, uint32_t b0, uint32_t b1) {
    asm volatile(
        "mma.sync.aligned.m16n8k16.row.col.f32.f16.f16.f32 "
        "{%0,%1,%2,%3}, {%4,%5,%6,%7}, {%8,%9}, {%0,%1,%2,%3};"
        : "+f"(d[0]), "+f"(d[1]), "+f"(d[2]), "+f"(d[3])
        : "r"(a[0]), "r"(a[1]), "r"(a[2]), "r"(a[3]), "r"(b0), "r"(b1));
}

// ---------------- device scratch ----------------
__device__ uint32_t g_xlh[MAXN*64];           // fp16 x_l image [n][64 half2-words]
__device__ float    g_xr[MAXN*D];
__device__ uint32_t g_xh[MAXN*64];            // fp16 x image (GEMM A operand)
__device__ int      g_rowptr[MAXN+1];
__device__ int      g_woff[MAXN];
__device__ int      g_adj[MAXE];
__device__ int      g_partials[128];
__device__ float    g_relproj[LAYERS*MAXR*D];
__device__ uint32_t g_bstage[LAYERS*256*64];  // fp16 dual-B images [n=256][kw=64]
__device__ uint32_t g_bproj[128*160];         // fp16 proj-B image  [n=128][kw=160]

// ---------------- CSR build ----------------
__global__ void hist_kernel(const int* __restrict__ dst, int* cnt, int e) {
    int i = blockIdx.x*blockDim.x + threadIdx.x;
    if (i < e) atomicAdd(&cnt[dst[i]], 1);
}

__global__ void scan1_kernel(const int* __restrict__ cnt, int* rowptr, int* partials, int n) {
    __shared__ int sh[1024];
    int i = blockIdx.x*1024 + threadIdx.x;
    int v = (i < n) ? cnt[i] : 0;
    sh[threadIdx.x] = v;
    __syncthreads();
    for (int off = 1; off < 1024; off <<= 1) {
        int t = (threadIdx.x >= off) ? sh[threadIdx.x - off] : 0;
        __syncthreads();
        sh[threadIdx.x] += t;
        __syncthreads();
    }
    if (i < n) rowptr[i] = sh[threadIdx.x] - v;
    if (threadIdx.x == 1023) partials[blockIdx.x] = sh[1023];
}

__global__ void scan2_kernel(int* partials, int* rowptr, int nb, int n, int total) {
    __shared__ int sh[128];
    int v = (threadIdx.x < nb) ? partials[threadIdx.x] : 0;
    sh[threadIdx.x] = v;
    __syncthreads();
    for (int off = 1; off < 128; off <<= 1) {
        int t = (threadIdx.x >= off) ? sh[threadIdx.x - off] : 0;
        __syncthreads();
        sh[threadIdx.x] += t;
        __syncthreads();
    }
    if (threadIdx.x < nb) partials[threadIdx.x] = sh[threadIdx.x] - v;
    if (threadIdx.x == 0) rowptr[n] = total;
}

__global__ void scan3_kernel(int* rowptr, const int* __restrict__ partials, int* woff, int n) {
    int i = blockIdx.x*blockDim.x + threadIdx.x;
    if (i < n) {
        int v = rowptr[i] + partials[i >> 10];
        rowptr[i] = v;
        woff[i] = v;
    }
}

__global__ void scatter_kernel(const int* __restrict__ src, const int* __restrict__ dst,
                               const int* __restrict__ etype, int* woff, int* adj, int e) {
    int i = blockIdx.x*blockDim.x + threadIdx.x;
    if (i < e) {
        int p = atomicAdd(&woff[dst[i]], 1);
        adj[p] = src[i] | (etype[i] << 20);
    }
}

// ---------------- rel_proj: 4 relations per block, 4-way ILP ----------------
__global__ void relproj_kernel(const float* __restrict__ rel, const float* __restrict__ we,
                               float* __restrict__ outp, int Rn) {
    int r0 = blockIdx.x * 4, l = blockIdx.y, c = threadIdx.x;
    __shared__ float sr[4][D];
#pragma unroll
    for (int j = 0; j < 4; j++) {
        int rr = r0 + j;
        sr[j][c] = (rr < Rn) ? rel[rr*D + c] : 0.f;
    }
    __syncthreads();
    const float* W = we + l*D*D;
    float a0 = 0.f, a1 = 0.f, a2 = 0.f, a3 = 0.f;
#pragma unroll 16
    for (int k = 0; k < D; k++) {
        float w = __ldg(&W[k*D + c]);
        a0 = fmaf(sr[0][k], w, a0);
        a1 = fmaf(sr[1][k], w, a1);
        a2 = fmaf(sr[2][k], w, a2);
        a3 = fmaf(sr[3][k], w, a3);
    }
    if (r0 + 0 < Rn) outp[(l*Rn + r0 + 0)*D + c] = a0;
    if (r0 + 1 < Rn) outp[(l*Rn + r0 + 1)*D + c] = a1;
    if (r0 + 2 < Rn) outp[(l*Rn + r0 + 2)*D + c] = a2;
    if (r0 + 3 < Rn) outp[(l*Rn + r0 + 3)*D + c] = a3;
}

// ---------------- B pre-stages (fp16 pairs) ----------------
__global__ void prep_b_kernel(const float* __restrict__ wl, const float* __restrict__ wr,
                              uint32_t* __restrict__ gB) {
    int nrow = blockIdx.x, l = blockIdx.y, kw = threadIdx.x;   // kw 0..63
    int c = nrow & 127;
    const float* W = (nrow < 128) ? (wl + l*D*D) : (wr + l*D*D);
    gB[l*16384 + nrow*64 + kw] = f2h2(W[(2*kw)*D + c], W[(2*kw+1)*D + c]);
}

__global__ void prep_bp_kernel(const float* __restrict__ pw, uint32_t* __restrict__ gBp, int F) {
    int nrow = blockIdx.x;        // 0..127
    int kw = threadIdx.x;         // 0..159
    float v0 = (2*kw     < F) ? pw[(2*kw)*128 + nrow]     : 0.f;
    float v1 = (2*kw + 1 < F) ? pw[(2*kw + 1)*128 + nrow] : 0.f;
    gBp[nrow*160 + kw] = f2h2(v0, v1);
}

// ---------------- fp16 proj GEMM -> writes fp16 x image ----------------
__global__ __launch_bounds__(256, 2) void proj_mma_kernel(
    const float* __restrict__ nf, const int* __restrict__ entity,
    const uint32_t* __restrict__ gBp, const float* __restrict__ pb,
    uint32_t* __restrict__ xh, int n, int F, int nTiles) {
    extern __shared__ uint32_t smu[];
    uint32_t* AsU = smu;                 // [2][64][PSTR]
    uint32_t* BsU = smu + PM_A_WORDS;    // [2][128][PSTR]
    int tid = threadIdx.x, lane = tid & 31, wid = tid >> 5;
    int wm = wid >> 2, wn = wid & 3;
    int lr = lane >> 2, lc = lane & 3;

    unsigned bbase = (unsigned)__cvta_generic_to_shared(BsU);

    float bjx[4], bjy[4];
#pragma unroll
    for (int nt = 0; nt < 4; nt++) {
        int col = wn*32 + nt*8 + 2*lc;
        bjx[nt] = pb[col];
        bjy[nt] = pb[col+1];
    }

    float4 aReg[4];
    auto loadA = [&](int t, int c) {
#pragma unroll
        for (int j = 0; j < 4; j++) {
            int q = tid + j*256;
            int r = q >> 4, k4 = q & 15;
            int gr = t*64 + r;
            int kg = c*64 + k4*4;
            aReg[j] = (gr < n && kg < F)
                ? *(const float4*)&nf[(long long)entity[gr]*F + kg]
                : make_float4(0,0,0,0);
        }
    };
    auto stsA = [&](int buf) {
#pragma unroll
        for (int j = 0; j < 4; j++) {
            int q = tid + j*256;
            int r = q >> 4, k4 = q & 15;
            uint2 w = make_uint2(f2h2(aReg[j].x, aReg[j].y), f2h2(aReg[j].z, aReg[j].w));
            *(uint2*)&AsU[buf*64*PSTR + r*PSTR + k4*2] = w;
        }
    };
    auto issueB = [&](int c, int buf) {
#pragma unroll
        for (int j = 0; j < 4; j++) {
            int q = tid + j*256;
            int row = q >> 3, seg = q & 7;
            cp_async16(bbase + (buf*128*PSTR + row*PSTR + seg*4)*4,
                       gBp + row*160 + c*32 + seg*4, 1);
        }
        cp_commit();
    };

    int tile0 = blockIdx.x;
    loadA(tile0, 0);
    issueB(0, 0);
    stsA(0);
    cp_wait0();
    __syncthreads();

    int buf = 0;
    for (int t = tile0; t < nTiles; t += gridDim.x) {
        float acc[2][4][4];
#pragma unroll
        for (int mt = 0; mt < 2; mt++)
#pragma unroll
            for (int nt = 0; nt < 4; nt++)
#pragma unroll
                for (int i = 0; i < 4; i++) acc[mt][nt][i] = 0.f;

#pragma unroll
        for (int c = 0; c < 5; c++) {
            int tn = (c < 4) ? t : t + gridDim.x;
            int cn = (c < 4) ? c + 1 : 0;
            bool hasNext = (c < 4) || (tn < nTiles);
            if (hasNext) { loadA(tn, cn); issueB(cn, buf ^ 1); }

            const uint32_t* Ab = &AsU[buf*64*PSTR];
            const uint32_t* Bb = &BsU[buf*128*PSTR];
#pragma unroll
            for (int kk = 0; kk < 4; kk++) {
                int kw0 = kk*8;
                uint32_t a[2][4];
#pragma unroll
                for (int mt = 0; mt < 2; mt++) {
                    int r = wm*32 + mt*16 + lr;
                    a[mt][0] = Ab[r*PSTR + kw0 + lc];
                    a[mt][1] = Ab[(r+8)*PSTR + kw0 + lc];
                    a[mt][2] = Ab[r*PSTR + kw0 + lc + 4];
                    a[mt][3] = Ab[(r+8)*PSTR + kw0 + lc + 4];
                }
#pragma unroll
                for (int nt = 0; nt < 4; nt++) {
                    int nrow = wn*32 + nt*8 + lr;
                    uint32_t b0 = Bb[nrow*PSTR + kw0 + lc];
                    uint32_t b1 = Bb[nrow*PSTR + kw0 + lc + 4];
                    mma_f16(acc[0][nt], a[0], b0, b1);
                    mma_f16(acc[1][nt], a[1], b0, b1);
                }
            }

            if (c == 4) {
#pragma unroll
                for (int mt = 0; mt < 2; mt++) {
                    int r1 = t*64 + wm*32 + mt*16 + lr;
#pragma unroll
                    for (int nt = 0; nt < 4; nt++) {
                        int col = wn*32 + nt*8 + 2*lc;
                        if (r1 < n)
                            xh[(size_t)r1*64 + (col>>1)] =
                                f2h2(acc[mt][nt][0] + bjx[nt], acc[mt][nt][1] + bjy[nt]);
                        if (r1 + 8 < n)
                            xh[(size_t)(r1+8)*64 + (col>>1)] =
                                f2h2(acc[mt][nt][2] + bjx[nt], acc[mt][nt][3] + bjy[nt]);
                    }
                }
            }

            if (hasNext) stsA(buf ^ 1);
            cp_wait0();
            __syncthreads();
            buf ^= 1;
        }
    }
}

// ---------------- fp16 dual GEMM: CTA 64x256, A via cp.async from xh ----------------
// outl -> fp16 image xlh; outr -> fp32 array
__global__ __launch_bounds__(256, 2) void gemm_dual_mma_kernel(
    const uint32_t* __restrict__ xh, const uint32_t* __restrict__ gB,
    const float* __restrict__ bl, const float* __restrict__ br,
    uint32_t* __restrict__ xlh, float* __restrict__ outr, int n, int nTiles) {
    extern __shared__ uint32_t smu[];
    uint32_t* AsU = smu;                       // [2][64][DSTR]
    uint32_t* BsU = smu + DA_WORDS;            // [256][DSTR]
    int tid = threadIdx.x, lane = tid & 31, wid = tid >> 5;
    int wm = wid >> 2, wn = wid & 3;
    int lr = lane >> 2, lc = lane & 3;

    unsigned abase = (unsigned)__cvta_generic_to_shared(AsU);

    {
        unsigned bbase = (unsigned)__cvta_generic_to_shared(BsU);
#pragma unroll
        for (int j = 0; j < 16; j++) {
            int q = tid + j*256;
            int row = q >> 4, seg = q & 15;
            cp_async16(bbase + (row*DSTR + seg*4)*4, gB + row*64 + seg*4, 1);
        }
    }

    auto issueA = [&](int t, int buf) {
#pragma unroll
        for (int j = 0; j < 4; j++) {
            int q = tid + j*256;
            int row = q >> 4, seg = q & 15;
            cp_async16(abase + (buf*64*DSTR + row*DSTR + seg*4)*4,
                       xh + (size_t)(t*64 + row)*64 + seg*4, 1);
        }
        cp_commit();
    };

    float bjx[8], bjy[8];
#pragma unroll
    for (int nt = 0; nt < 8; nt++) {
        int col = wn*64 + nt*8 + 2*lc;
        const float* bv = (col < 128) ? bl : br;
        int c = col & 127;
        bjx[nt] = bv[c];
        bjy[nt] = bv[c+1];
    }

    int tile0 = blockIdx.x;
    issueA(tile0, 0);
    cp_wait0();
    __syncthreads();

    int buf = 0;
    for (int t = tile0; t < nTiles; t += gridDim.x, buf ^= 1) {
        int tn = t + gridDim.x;
        if (tn < nTiles) issueA(tn, buf ^ 1);

        float acc[2][8][4];
#pragma unroll
        for (int mt = 0; mt < 2; mt++)
#pragma unroll
            for (int nt = 0; nt < 8; nt++)
#pragma unroll
                for (int i = 0; i < 4; i++) acc[mt][nt][i] = 0.f;

        const uint32_t* Ab = &AsU[buf*64*DSTR];
#pragma unroll
        for (int kk = 0; kk < 8; kk++) {
            int kw0 = kk*8;
            uint32_t a[2][4];
#pragma unroll
            for (int mt = 0; mt < 2; mt++) {
                int r = wm*32 + mt*16 + lr;
                a[mt][0] = Ab[r*DSTR + kw0 + lc];
                a[mt][1] = Ab[(r+8)*DSTR + kw0 + lc];
                a[mt][2] = Ab[r*DSTR + kw0 + lc + 4];
                a[mt][3] = Ab[(r+8)*DSTR + kw0 + lc + 4];
            }
#pragma unroll
            for (int nt = 0; nt < 8; nt++) {
                int nrow = wn*64 + nt*8 + lr;
                uint32_t b0 = BsU[nrow*DSTR + kw0 + lc];
                uint32_t b1 = BsU[nrow*DSTR + kw0 + lc + 4];
                mma_f16(acc[0][nt], a[0], b0, b1);
                mma_f16(acc[1][nt], a[1], b0, b1);
            }
        }

#pragma unroll
        for (int mt = 0; mt < 2; mt++) {
            int r1 = t*64 + wm*32 + mt*16 + lr;
#pragma unroll
            for (int nt = 0; nt < 8; nt++) {
                int col = wn*64 + nt*8 + 2*lc;
                if (col < 128) {
                    // xl -> fp16 image
                    if (r1 < n)
                        xlh[(size_t)r1*64 + (col>>1)] =
                            f2h2(acc[mt][nt][0] + bjx[nt], acc[mt][nt][1] + bjy[nt]);
                    if (r1 + 8 < n)
                        xlh[(size_t)(r1+8)*64 + (col>>1)] =
                            f2h2(acc[mt][nt][2] + bjx[nt], acc[mt][nt][3] + bjy[nt]);
                } else {
                    int c = col & 127;
                    if (r1 < n)
                        *(float2*)&outr[r1*128 + c] =
                            make_float2(acc[mt][nt][0] + bjx[nt], acc[mt][nt][1] + bjy[nt]);
                    if (r1 + 8 < n)
                        *(float2*)&outr[(r1+8)*128 + c] =
                            make_float2(acc[mt][nt][2] + bjx[nt], acc[mt][nt][3] + bjy[nt]);
                }
            }
        }

        cp_wait0();
        __syncthreads();
    }
}

// ---------------- fused GATv2 attention + softmax + aggregation ----------------
// xl gathered from fp16 image (256B/edge instead of 512B)
__global__ __launch_bounds__(256) void gat_agg_kernel(
    const uint32_t* __restrict__ xlh, const float* __restrict__ xr,
    const int* __restrict__ rowptr, const int* __restrict__ adj,
    const float* __restrict__ relproj, const float* __restrict__ att,
    const float* __restrict__ bias, float* __restrict__ out,
    uint32_t* __restrict__ xh, int n, int do_elu) {
    int warp = (blockIdx.x*blockDim.x + threadIdx.x) >> 5;
    if (warp >= n) return;
    int lane = threadIdx.x & 31;
    int c0 = lane * 4;

    const float4 attv = *(const float4*)&att[c0];
    const float4 xrv  = *(const float4*)&xr[warp*D + c0];
    float4 acc = make_float4(0.f, 0.f, 0.f, 0.f);
    float s = 0.f;

    int e0 = rowptr[warp], e1 = rowptr[warp+1];
    int e = e0;
    for (; e + 4 <= e1; e += 4) {
        int p[4];
        float4 xv[4], rv[4];
#pragma unroll
        for (int i = 0; i < 4; i++) p[i] = __ldg(&adj[e+i]);
#pragma unroll
        for (int i = 0; i < 4; i++) {
            uint2 w = ldnc2u(&xlh[(size_t)(p[i] & 0xFFFFF)*64 + lane*2]);
            float2 lo = h22f2(w.x), hi = h22f2(w.y);
            xv[i] = make_float4(lo.x, lo.y, hi.x, hi.y);
            rv[i] = *(const float4*)&relproj[(p[i] >> 20)*D + c0];
        }
        float d[4];
#pragma unroll
        for (int i = 0; i < 4; i++) {
            float m0 = xv[i].x + xrv.x + rv[i].x;
            float m1 = xv[i].y + xrv.y + rv[i].y;
            float m2 = xv[i].z + xrv.z + rv[i].z;
            float m3 = xv[i].w + xrv.w + rv[i].w;
            float dd =        fmaf(0.4f, fabsf(m0), 0.6f*m0) * attv.x;
            dd = fmaf(fmaf(0.4f, fabsf(m1), 0.6f*m1), attv.y, dd);
            dd = fmaf(fmaf(0.4f, fabsf(m2), 0.6f*m2), attv.z, dd);
            dd = fmaf(fmaf(0.4f, fabsf(m3), 0.6f*m3), attv.w, dd);
            d[i] = dd;
        }
#pragma unroll
        for (int i = 0; i < 4; i++) d[i] += __shfl_xor_sync(0xffffffffu, d[i], 1);
#pragma unroll
        for (int i = 0; i < 4; i++) d[i] += __shfl_xor_sync(0xffffffffu, d[i], 2);
#pragma unroll
        for (int i = 0; i < 4; i++) d[i] += __shfl_xor_sync(0xffffffffu, d[i], 4);

        float w0 = __expf(d[0]), w1 = __expf(d[1]);
        float w2 = __expf(d[2]), w3 = __expf(d[3]);
        s += (w0 + w1) + (w2 + w3);
        acc.x += fmaf(w0, xv[0].x, w1*xv[1].x) + fmaf(w2, xv[2].x, w3*xv[3].x);
        acc.y += fmaf(w0, xv[0].y, w1*xv[1].y) + fmaf(w2, xv[2].y, w3*xv[3].y);
        acc.z += fmaf(w0, xv[0].z, w1*xv[1].z) + fmaf(w2, xv[2].z, w3*xv[3].z);
        acc.w += fmaf(w0, xv[0].w, w1*xv[1].w) + fmaf(w2, xv[2].w, w3*xv[3].w);
    }
    for (; e < e1; e++) {
        int p0 = __ldg(&adj[e]);
        uint2 w = ldnc2u(&xlh[(size_t)(p0 & 0xFFFFF)*64 + lane*2]);
        float2 lo = h22f2(w.x), hi = h22f2(w.y);
        float4 x0 = make_float4(lo.x, lo.y, hi.x, hi.y);
        float4 r0 = *(const float4*)&relproj[(p0 >> 20)*D + c0];
        float m0 = x0.x + xrv.x + r0.x, m1 = x0.y + xrv.y + r0.y;
        float m2 = x0.z + xrv.z + r0.z, m3 = x0.w + xrv.w + r0.w;
        float d0 =        fmaf(0.4f, fabsf(m0), 0.6f*m0) * attv.x;
        d0 = fmaf(fmaf(0.4f, fabsf(m1), 0.6f*m1), attv.y, d0);
        d0 = fmaf(fmaf(0.4f, fabsf(m2), 0.6f*m2), attv.z, d0);
        d0 = fmaf(fmaf(0.4f, fabsf(m3), 0.6f*m3), attv.w, d0);
        d0 += __shfl_xor_sync(0xffffffffu, d0, 1);
        d0 += __shfl_xor_sync(0xffffffffu, d0, 2);
        d0 += __shfl_xor_sync(0xffffffffu, d0, 4);
        float w0 = __expf(d0);
        s += w0;
        acc.x = fmaf(w0, x0.x, acc.x);
        acc.y = fmaf(w0, x0.y, acc.y);
        acc.z = fmaf(w0, x0.z, acc.z);
        acc.w = fmaf(w0, x0.w, acc.w);
    }

    float inv = (s > 0.f) ? (1.f / s) : 0.f;
    float4 bj = *(const float4*)&bias[c0];
    float4 r;
    r.x = fmaf(acc.x, inv, bj.x);
    r.y = fmaf(acc.y, inv, bj.y);
    r.z = fmaf(acc.z, inv, bj.z);
    r.w = fmaf(acc.w, inv, bj.w);
    if (do_elu) {
        r.x = (r.x > 0.f) ? r.x : (__expf(r.x) - 1.f);
        r.y = (r.y > 0.f) ? r.y : (__expf(r.y) - 1.f);
        r.z = (r.z > 0.f) ? r.z : (__expf(r.z) - 1.f);
        r.w = (r.w > 0.f) ? r.w : (__expf(r.w) - 1.f);
    }
    if (xh) {
        uint2 w = make_uint2(f2h2(r.x, r.y), f2h2(r.z, r.w));
        *(uint2*)&xh[(size_t)warp*64 + lane*2] = w;
    } else {
        *(float4*)&out[warp*D + c0] = r;
    }
}

// ---------------- launch ----------------
extern "C" void kernel_launch(void* const* d_in, const int* in_sizes, int n_in,
                              void* d_out, int out_size) {
    const int*   entity = (const int*)  d_in[0];
    const int*   eidx   = (const int*)  d_in[1];
    const int*   etype  = (const int*)  d_in[2];
    const float* nf     = (const float*)d_in[3];
    const float* rel    = (const float*)d_in[4];
    const float* pw     = (const float*)d_in[5];
    const float* pb     = (const float*)d_in[6];
    const float* wl     = (const float*)d_in[7];
    const float* bl     = (const float*)d_in[8];
    const float* wr     = (const float*)d_in[9];
    const float* brr    = (const float*)d_in[10];
    const float* we     = (const float*)d_in[11];
    const float* att    = (const float*)d_in[12];
    const float* bias   = (const float*)d_in[13];
    float* out = (float*)d_out;

    int n  = in_sizes[0];
    int e  = in_sizes[2];
    int Rn = in_sizes[4] / D;
    int F  = in_sizes[3] / n;
    const int* srcp = eidx;
    const int* dstp = eidx + e;

    float *pxr, *prelp;
    uint32_t *pxlh, *pbst, *pbpj, *pxh;
    int *prow, *pwoff, *padj, *ppart;
    cudaGetSymbolAddress((void**)&pxlh,  g_xlh);
    cudaGetSymbolAddress((void**)&pxr,   g_xr);
    cudaGetSymbolAddress((void**)&pxh,   g_xh);
    cudaGetSymbolAddress((void**)&prelp, g_relproj);
    cudaGetSymbolAddress((void**)&pbst,  g_bstage);
    cudaGetSymbolAddress((void**)&pbpj,  g_bproj);
    cudaGetSymbolAddress((void**)&prow,  g_rowptr);
    cudaGetSymbolAddress((void**)&pwoff, g_woff);
    cudaGetSymbolAddress((void**)&padj,  g_adj);
    cudaGetSymbolAddress((void**)&ppart, g_partials);

    int nsm = 148;
    cudaDeviceGetAttribute(&nsm, cudaDevAttrMultiProcessorCount, 0);

    cudaFuncSetAttribute(proj_mma_kernel, cudaFuncAttributeMaxDynamicSharedMemorySize, PM_SMEM);
    cudaFuncSetAttribute(gemm_dual_mma_kernel, cudaFuncAttributeMaxDynamicSharedMemorySize, MMA_SMEM);

    int nTiles = (n + 63) / 64;
    int projGrid = (nTiles < 2*nsm) ? nTiles : 2*nsm;
    int dualGrid = (nTiles < 2*nsm) ? nTiles : 2*nsm;
    int aggBlocks = (n*32 + 255) / 256;
    int nb = (n + 1023) / 1024;

    // single stream, round-9 order (dual L0 at profiled slot)
    cudaMemsetAsync(pwoff, 0, (size_t)n * sizeof(int));                                   // 1
    prep_bp_kernel<<<128, 160>>>(pw, pbpj, F);                                            // 2
    prep_b_kernel<<<dim3(256, LAYERS), 64>>>(wl, wr, pbst);                               // 3
    proj_mma_kernel<<<projGrid, 256, PM_SMEM>>>(nf, entity, pbpj, pb, pxh, n, F, nTiles); // 4
    gemm_dual_mma_kernel<<<dualGrid, 256, MMA_SMEM>>>(pxh, pbst, bl, brr,
                                                      pxlh, pxr, n, nTiles);              // 5 <- profiled
    relproj_kernel<<<dim3((Rn + 3)/4, LAYERS), D>>>(rel, we, prelp, Rn);
    hist_kernel<<<(e+255)/256, 256>>>(dstp, pwoff, e);
    scan1_kernel<<<nb, 1024>>>(pwoff, prow, ppart, n);
    scan2_kernel<<<1, 128>>>(ppart, prow, nb, n, e);
    scan3_kernel<<<(n+255)/256, 256>>>(prow, ppart, pwoff, n);
    scatter_kernel<<<(e+255)/256, 256>>>(srcp, dstp, etype, pwoff, padj, e);

    // layer 0 aggregation -> fp16 x image (feeds dual L1)
    gat_agg_kernel<<<aggBlocks, 256>>>(pxlh, pxr, prow, padj, prelp, att, bias,
                                       out, pxh, n, 1);

    // layer 1
    gemm_dual_mma_kernel<<<dualGrid, 256, MMA_SMEM>>>(pxh, pbst + 16384, bl + D, brr + D,
                                                      pxlh, pxr, n, nTiles);
    gat_agg_kernel<<<aggBlocks, 256>>>(pxlh, pxr, prow, padj, prelp + Rn*D, att + D, bias + D,
                                       out, (uint32_t*)nullptr, n, 0);
}

// round 12
// speedup vs baseline: 1.2531x; 1.0817x over previous
#include <cuda_runtime.h>
#include <cuda_fp16.h>
#include <math.h>
#include <stdint.h>

#define D       128
#define NHEADS  4
#define MAXN    50048
#define MAXE    640000
#define MAXR    256
#define LAYERS  2

// fp16 dual GEMM: CTA tile M=64, N=256, A via cp.async from fp16 x image.
#define DSTR 68
#define DA_WORDS (2*64*DSTR)
#define DB_WORDS (256*DSTR)
#define MMA_SMEM ((DA_WORDS + DB_WORDS)*4)    // 104448 -> 2 CTAs/SM

// fp16 proj GEMM: CTA tile M=64, N=128, K=320 in 5 chunks of 64
#define PSTR 36
#define PM_A_WORDS (2*64*PSTR)
#define PM_B_WORDS (2*128*PSTR)
#define PM_SMEM ((PM_A_WORDS + PM_B_WORDS)*4) // 55296

// ---------------- helpers ----------------
__device__ __forceinline__ void cp_async16(unsigned saddr, const void* gaddr, int valid) {
    asm volatile("cp.async.ca.shared.global [%0], [%1], 16, %2;"
                 :: "r"(saddr), "l"(gaddr), "r"(valid ? 16 : 0));
}
__device__ __forceinline__ void cp_commit() { asm volatile("cp.async.commit_group;"); }
__device__ __forceinline__ void cp_wait0()  { asm volatile("cp.async.wait_group 0;"); }

__device__ __forceinline__ uint2 ldnc2u(const uint32_t* p) {
    uint2 v;
    asm volatile("ld.global.nc.L1::no_allocate.v2.u32 {%0,%1}, [%2];"
                 : "=r"(v.x), "=r"(v.y) : "l"(p));
    return v;
}

__device__ __forceinline__ uint32_t f2h2(float lo, float hi) {
    __half2 h = __floats2half2_rn(lo, hi);
    return *(uint32_t*)&h;
}
__device__ __forceinline__ float2 h22f2(uint32_t w) {
    return __half22float2(*(__half2*)&w);
}
__device__ __forceinline__ __half2 u2h(uint32_t w) { return *(__half2*)&w; }
__device__ __forceinline__ uint32_t h2u(__half2 h) { return *(uint32_t*)&h; }

// m16n8k16 fp16 MMA, fp32 accumulate
__device__ __forceinline__ void mma_f16(float* d, const uint32_t* a, uint32_t b0, uint32_t b1) {
    asm volatile(
        "mma.sync.aligned.m16n8k16.row.col.f32.f16.f16.f32 "
        "{%0,%1,%2,%3}, {%4,%5,%6,%7}, {%8,%9}, {%0,%1,%2,%3};"
        : "+f"(d[0]), "+f"(d[1]), "+f"(d[2]), "+f"(d[3])
        : "r"(a[0]), "r"(a[1]), "r"(a[2]), "r"(a[3]), "r"(b0), "r"(b1));
}

// ---------------- device scratch ----------------
__device__ uint32_t g_xlh[MAXN*64];           // fp16 x_l image [n][64 half2-words]
__device__ float    g_xr[MAXN*D];
__device__ uint32_t g_xh[MAXN*64];            // fp16 x image (GEMM A operand)
__device__ int      g_rowptr[MAXN+1];
__device__ int      g_woff[MAXN];
__device__ int      g_adj[MAXE];
__device__ int      g_partials[128];
__device__ uint32_t g_relh[LAYERS*MAXR*64];   // fp16 relproj image [l][r][64 half2-words]
__device__ uint32_t g_bstage[LAYERS*256*64];
__device__ uint32_t g_bproj[128*160];

// ---------------- CSR build ----------------
__global__ void hist_kernel(const int* __restrict__ dst, int* cnt, int e) {
    int i = blockIdx.x*blockDim.x + threadIdx.x;
    if (i < e) atomicAdd(&cnt[dst[i]], 1);
}

__global__ void scan1_kernel(const int* __restrict__ cnt, int* rowptr, int* partials, int n) {
    __shared__ int sh[1024];
    int i = blockIdx.x*1024 + threadIdx.x;
    int v = (i < n) ? cnt[i] : 0;
    sh[threadIdx.x] = v;
    __syncthreads();
    for (int off = 1; off < 1024; off <<= 1) {
        int t = (threadIdx.x >= off) ? sh[threadIdx.x - off] : 0;
        __syncthreads();
        sh[threadIdx.x] += t;
        __syncthreads();
    }
    if (i < n) rowptr[i] = sh[threadIdx.x] - v;
    if (threadIdx.x == 1023) partials[blockIdx.x] = sh[1023];
}

__global__ void scan2_kernel(int* partials, int* rowptr, int nb, int n, int total) {
    __shared__ int sh[128];
    int v = (threadIdx.x < nb) ? partials[threadIdx.x] : 0;
    sh[threadIdx.x] = v;
    __syncthreads();
    for (int off = 1; off < 128; off <<= 1) {
        int t = (threadIdx.x >= off) ? sh[threadIdx.x - off] : 0;
        __syncthreads();
        sh[threadIdx.x] += t;
        __syncthreads();
    }
    if (threadIdx.x < nb) partials[threadIdx.x] = sh[threadIdx.x] - v;
    if (threadIdx.x == 0) rowptr[n] = total;
}

__global__ void scan3_kernel(int* rowptr, const int* __restrict__ partials, int* woff, int n) {
    int i = blockIdx.x*blockDim.x + threadIdx.x;
    if (i < n) {
        int v = rowptr[i] + partials[i >> 10];
        rowptr[i] = v;
        woff[i] = v;
    }
}

__global__ void scatter_kernel(const int* __restrict__ src, const int* __restrict__ dst,
                               const int* __restrict__ etype, int* woff, int* adj, int e) {
    int i = blockIdx.x*blockDim.x + threadIdx.x;
    if (i < e) {
        int p = atomicAdd(&woff[dst[i]], 1);
        adj[p] = src[i] | (etype[i] << 20);
    }
}

// ---------------- rel_proj -> fp16 image; 4 relations per block, 2 channels/thread ----------------
__global__ void relproj_kernel(const float* __restrict__ rel, const float* __restrict__ we,
                               uint32_t* __restrict__ outp, int Rn) {
    int r0 = blockIdx.x * 4, l = blockIdx.y, c2 = threadIdx.x;  // c2: 0..63
    __shared__ float sr[4][D];
#pragma unroll
    for (int j = 0; j < 8; j++) {
        int q = j*64 + c2;              // 0..511
        int row = q >> 7, ch = q & 127;
        int rr = r0 + row;
        sr[row][ch] = (rr < Rn) ? rel[rr*D + ch] : 0.f;
    }
    __syncthreads();
    const float* W = we + l*D*D;
    float a[4][2];
#pragma unroll
    for (int j = 0; j < 4; j++) { a[j][0] = 0.f; a[j][1] = 0.f; }
#pragma unroll 8
    for (int k = 0; k < D; k++) {
        float w0 = __ldg(&W[k*D + 2*c2]);
        float w1 = __ldg(&W[k*D + 2*c2 + 1]);
#pragma unroll
        for (int j = 0; j < 4; j++) {
            a[j][0] = fmaf(sr[j][k], w0, a[j][0]);
            a[j][1] = fmaf(sr[j][k], w1, a[j][1]);
        }
    }
#pragma unroll
    for (int j = 0; j < 4; j++)
        if (r0 + j < Rn)
            outp[(l*Rn + r0 + j)*64 + c2] = f2h2(a[j][0], a[j][1]);
}

// ---------------- B pre-stages (fp16 pairs) ----------------
__global__ void prep_b_kernel(const float* __restrict__ wl, const float* __restrict__ wr,
                              uint32_t* __restrict__ gB) {
    int nrow = blockIdx.x, l = blockIdx.y, kw = threadIdx.x;
    int c = nrow & 127;
    const float* W = (nrow < 128) ? (wl + l*D*D) : (wr + l*D*D);
    gB[l*16384 + nrow*64 + kw] = f2h2(W[(2*kw)*D + c], W[(2*kw+1)*D + c]);
}

__global__ void prep_bp_kernel(const float* __restrict__ pw, uint32_t* __restrict__ gBp, int F) {
    int nrow = blockIdx.x;
    int kw = threadIdx.x;
    float v0 = (2*kw     < F) ? pw[(2*kw)*128 + nrow]     : 0.f;
    float v1 = (2*kw + 1 < F) ? pw[(2*kw + 1)*128 + nrow] : 0.f;
    gBp[nrow*160 + kw] = f2h2(v0, v1);
}

// ---------------- fp16 proj GEMM -> writes fp16 x image ----------------
__global__ __launch_bounds__(256, 2) void proj_mma_kernel(
    const float* __restrict__ nf, const int* __restrict__ entity,
    const uint32_t* __restrict__ gBp, const float* __restrict__ pb,
    uint32_t* __restrict__ xh, int n, int F, int nTiles) {
    extern __shared__ uint32_t smu[];
    uint32_t* AsU = smu;
    uint32_t* BsU = smu + PM_A_WORDS;
    int tid = threadIdx.x, lane = tid & 31, wid = tid >> 5;
    int wm = wid >> 2, wn = wid & 3;
    int lr = lane >> 2, lc = lane & 3;

    unsigned bbase = (unsigned)__cvta_generic_to_shared(BsU);

    float bjx[4], bjy[4];
#pragma unroll
    for (int nt = 0; nt < 4; nt++) {
        int col = wn*32 + nt*8 + 2*lc;
        bjx[nt] = pb[col];
        bjy[nt] = pb[col+1];
    }

    float4 aReg[4];
    auto loadA = [&](int t, int c) {
#pragma unroll
        for (int j = 0; j < 4; j++) {
            int q = tid + j*256;
            int r = q >> 4, k4 = q & 15;
            int gr = t*64 + r;
            int kg = c*64 + k4*4;
            aReg[j] = (gr < n && kg < F)
                ? *(const float4*)&nf[(long long)entity[gr]*F + kg]
                : make_float4(0,0,0,0);
        }
    };
    auto stsA = [&](int buf) {
#pragma unroll
        for (int j = 0; j < 4; j++) {
            int q = tid + j*256;
            int r = q >> 4, k4 = q & 15;
            uint2 w = make_uint2(f2h2(aReg[j].x, aReg[j].y), f2h2(aReg[j].z, aReg[j].w));
            *(uint2*)&AsU[buf*64*PSTR + r*PSTR + k4*2] = w;
        }
    };
    auto issueB = [&](int c, int buf) {
#pragma unroll
        for (int j = 0; j < 4; j++) {
            int q = tid + j*256;
            int row = q >> 3, seg = q & 7;
            cp_async16(bbase + (buf*128*PSTR + row*PSTR + seg*4)*4,
                       gBp + row*160 + c*32 + seg*4, 1);
        }
        cp_commit();
    };

    int tile0 = blockIdx.x;
    loadA(tile0, 0);
    issueB(0, 0);
    stsA(0);
    cp_wait0();
    __syncthreads();

    int buf = 0;
    for (int t = tile0; t < nTiles; t += gridDim.x) {
        float acc[2][4][4];
#pragma unroll
        for (int mt = 0; mt < 2; mt++)
#pragma unroll
            for (int nt = 0; nt < 4; nt++)
#pragma unroll
                for (int i = 0; i < 4; i++) acc[mt][nt][i] = 0.f;

#pragma unroll
        for (int c = 0; c < 5; c++) {
            int tn = (c < 4) ? t : t + gridDim.x;
            int cn = (c < 4) ? c + 1 : 0;
            bool hasNext = (c < 4) || (tn < nTiles);
            if (hasNext) { loadA(tn, cn); issueB(cn, buf ^ 1); }

            const uint32_t* Ab = &AsU[buf*64*PSTR];
            const uint32_t* Bb = &BsU[buf*128*PSTR];
#pragma unroll
            for (int kk = 0; kk < 4; kk++) {
                int kw0 = kk*8;
                uint32_t a[2][4];
#pragma unroll
                for (int mt = 0; mt < 2; mt++) {
                    int r = wm*32 + mt*16 + lr;
                    a[mt][0] = Ab[r*PSTR + kw0 + lc];
                    a[mt][1] = Ab[(r+8)*PSTR + kw0 + lc];
                    a[mt][2] = Ab[r*PSTR + kw0 + lc + 4];
                    a[mt][3] = Ab[(r+8)*PSTR + kw0 + lc + 4];
                }
#pragma unroll
                for (int nt = 0; nt < 4; nt++) {
                    int nrow = wn*32 + nt*8 + lr;
                    uint32_t b0 = Bb[nrow*PSTR + kw0 + lc];
                    uint32_t b1 = Bb[nrow*PSTR + kw0 + lc + 4];
                    mma_f16(acc[0][nt], a[0], b0, b1);
                    mma_f16(acc[1][nt], a[1], b0, b1);
                }
            }

            if (c == 4) {
#pragma unroll
                for (int mt = 0; mt < 2; mt++) {
                    int r1 = t*64 + wm*32 + mt*16 + lr;
#pragma unroll
                    for (int nt = 0; nt < 4; nt++) {
                        int col = wn*32 + nt*8 + 2*lc;
                        if (r1 < n)
                            xh[(size_t)r1*64 + (col>>1)] =
                                f2h2(acc[mt][nt][0] + bjx[nt], acc[mt][nt][1] + bjy[nt]);
                        if (r1 + 8 < n)
                            xh[(size_t)(r1+8)*64 + (col>>1)] =
                                f2h2(acc[mt][nt][2] + bjx[nt], acc[mt][nt][3] + bjy[nt]);
                    }
                }
            }

            if (hasNext) stsA(buf ^ 1);
            cp_wait0();
            __syncthreads();
            buf ^= 1;
        }
    }
}

// ---------------- fp16 dual GEMM: CTA 64x256, A via cp.async from xh ----------------
__global__ __launch_bounds__(256, 2) void gemm_dual_mma_kernel(
    const uint32_t* __restrict__ xh, const uint32_t* __restrict__ gB,
    const float* __restrict__ bl, const float* __restrict__ br,
    uint32_t* __restrict__ xlh, float* __restrict__ outr, int n, int nTiles) {
    extern __shared__ uint32_t smu[];
    uint32_t* AsU = smu;
    uint32_t* BsU = smu + DA_WORDS;
    int tid = threadIdx.x, lane = tid & 31, wid = tid >> 5;
    int wm = wid >> 2, wn = wid & 3;
    int lr = lane >> 2, lc = lane & 3;

    unsigned abase = (unsigned)__cvta_generic_to_shared(AsU);

    {
        unsigned bbase = (unsigned)__cvta_generic_to_shared(BsU);
#pragma unroll
        for (int j = 0; j < 16; j++) {
            int q = tid + j*256;
            int row = q >> 4, seg = q & 15;
            cp_async16(bbase + (row*DSTR + seg*4)*4, gB + row*64 + seg*4, 1);
        }
    }

    auto issueA = [&](int t, int buf) {
#pragma unroll
        for (int j = 0; j < 4; j++) {
            int q = tid + j*256;
            int row = q >> 4, seg = q & 15;
            cp_async16(abase + (buf*64*DSTR + row*DSTR + seg*4)*4,
                       xh + (size_t)(t*64 + row)*64 + seg*4, 1);
        }
        cp_commit();
    };

    float bjx[8], bjy[8];
#pragma unroll
    for (int nt = 0; nt < 8; nt++) {
        int col = wn*64 + nt*8 + 2*lc;
        const float* bv = (col < 128) ? bl : br;
        int c = col & 127;
        bjx[nt] = bv[c];
        bjy[nt] = bv[c+1];
    }

    int tile0 = blockIdx.x;
    issueA(tile0, 0);
    cp_wait0();
    __syncthreads();

    int buf = 0;
    for (int t = tile0; t < nTiles; t += gridDim.x, buf ^= 1) {
        int tn = t + gridDim.x;
        if (tn < nTiles) issueA(tn, buf ^ 1);

        float acc[2][8][4];
#pragma unroll
        for (int mt = 0; mt < 2; mt++)
#pragma unroll
            for (int nt = 0; nt < 8; nt++)
#pragma unroll
                for (int i = 0; i < 4; i++) acc[mt][nt][i] = 0.f;

        const uint32_t* Ab = &AsU[buf*64*DSTR];
#pragma unroll
        for (int kk = 0; kk < 8; kk++) {
            int kw0 = kk*8;
            uint32_t a[2][4];
#pragma unroll
            for (int mt = 0; mt < 2; mt++) {
                int r = wm*32 + mt*16 + lr;
                a[mt][0] = Ab[r*DSTR + kw0 + lc];
                a[mt][1] = Ab[(r+8)*DSTR + kw0 + lc];
                a[mt][2] = Ab[r*DSTR + kw0 + lc + 4];
                a[mt][3] = Ab[(r+8)*DSTR + kw0 + lc + 4];
            }
#pragma unroll
            for (int nt = 0; nt < 8; nt++) {
                int nrow = wn*64 + nt*8 + lr;
                uint32_t b0 = BsU[nrow*DSTR + kw0 + lc];
                uint32_t b1 = BsU[nrow*DSTR + kw0 + lc + 4];
                mma_f16(acc[0][nt], a[0], b0, b1);
                mma_f16(acc[1][nt], a[1], b0, b1);
            }
        }

#pragma unroll
        for (int mt = 0; mt < 2; mt++) {
            int r1 = t*64 + wm*32 + mt*16 + lr;
#pragma unroll
            for (int nt = 0; nt < 8; nt++) {
                int col = wn*64 + nt*8 + 2*lc;
                if (col < 128) {
                    if (r1 < n)
                        xlh[(size_t)r1*64 + (col>>1)] =
                            f2h2(acc[mt][nt][0] + bjx[nt], acc[mt][nt][1] + bjy[nt]);
                    if (r1 + 8 < n)
                        xlh[(size_t)(r1+8)*64 + (col>>1)] =
                            f2h2(acc[mt][nt][2] + bjx[nt], acc[mt][nt][3] + bjy[nt]);
                } else {
                    int c = col & 127;
                    if (r1 < n)
                        *(float2*)&outr[r1*128 + c] =
                            make_float2(acc[mt][nt][0] + bjx[nt], acc[mt][nt][1] + bjy[nt]);
                    if (r1 + 8 < n)
                        *(float2*)&outr[(r1+8)*128 + c] =
                            make_float2(acc[mt][nt][2] + bjx[nt], acc[mt][nt][3] + bjy[nt]);
                }
            }
        }

        cp_wait0();
        __syncthreads();
    }
}

// ---------------- fused GATv2 attention + softmax + aggregation (half2 math) ----------------
__global__ __launch_bounds__(256) void gat_agg_kernel(
    const uint32_t* __restrict__ xlh, const float* __restrict__ xr,
    const int* __restrict__ rowptr, const int* __restrict__ adj,
    const uint32_t* __restrict__ relh, const float* __restrict__ att,
    const float* __restrict__ bias, float* __restrict__ out,
    uint32_t* __restrict__ xh, int n, int do_elu) {
    int warp = (blockIdx.x*blockDim.x + threadIdx.x) >> 5;
    if (warp >= n) return;
    unsigned lane = threadIdx.x & 31;
    unsigned lane2 = lane * 2;
    int c0 = lane * 4;

    const float4 attv = *(const float4*)&att[c0];
    const float4 xrv  = *(const float4*)&xr[warp*D + c0];
    const __half2 hatt0 = u2h(f2h2(attv.x, attv.y));
    const __half2 hatt1 = u2h(f2h2(attv.z, attv.w));
    const __half2 hxr0  = u2h(f2h2(xrv.x, xrv.y));
    const __half2 hxr1  = u2h(f2h2(xrv.z, xrv.w));
    const __half2 C06 = __floats2half2_rn(0.6f, 0.6f);
    const __half2 C04 = __floats2half2_rn(0.4f, 0.4f);

    float4 acc = make_float4(0.f, 0.f, 0.f, 0.f);
    float s = 0.f;

    int e0 = rowptr[warp], e1 = rowptr[warp+1];
    int e = e0;
    for (; e + 4 <= e1; e += 4) {
        int p[4];
        uint2 xw[4], rw[4];
#pragma unroll
        for (int i = 0; i < 4; i++) p[i] = __ldg(&adj[e+i]);
#pragma unroll
        for (int i = 0; i < 4; i++) {
            unsigned src = (unsigned)p[i] & 0xFFFFFu;
            unsigned t   = (unsigned)p[i] >> 20;
            xw[i] = ldnc2u(&xlh[src*64u + lane2]);
            rw[i] = *(const uint2*)&relh[t*64u + lane2];
        }
        float d[4];
#pragma unroll
        for (int i = 0; i < 4; i++) {
            __half2 m0 = __hadd2(u2h(xw[i].x), __hadd2(hxr0, u2h(rw[i].x)));
            __half2 m1 = __hadd2(u2h(xw[i].y), __hadd2(hxr1, u2h(rw[i].y)));
            __half2 l0 = __hfma2(m0, C06, __hmul2(__habs2(m0), C04));
            __half2 l1 = __hfma2(m1, C06, __hmul2(__habs2(m1), C04));
            __half2 dh = __hfma2(l1, hatt1, __hmul2(l0, hatt0));
            float2 df = __half22float2(dh);
            d[i] = df.x + df.y;
        }
        // pack 2 logits per word; butterfly over 8-lane octet in half2
        uint32_t q0 = f2h2(d[0], d[1]);
        uint32_t q1 = f2h2(d[2], d[3]);
#pragma unroll
        for (int off = 1; off <= 4; off <<= 1) {
            uint32_t t0 = __shfl_xor_sync(0xffffffffu, q0, off);
            uint32_t t1 = __shfl_xor_sync(0xffffffffu, q1, off);
            q0 = h2u(__hadd2(u2h(q0), u2h(t0)));
            q1 = h2u(__hadd2(u2h(q1), u2h(t1)));
        }
        float2 e01 = h22f2(q0), e23 = h22f2(q1);
        float w0 = __expf(e01.x), w1 = __expf(e01.y);
        float w2 = __expf(e23.x), w3 = __expf(e23.y);
        s += (w0 + w1) + (w2 + w3);
        float2 x0l = h22f2(xw[0].x), x0h = h22f2(xw[0].y);
        float2 x1l = h22f2(xw[1].x), x1h = h22f2(xw[1].y);
        float2 x2l = h22f2(xw[2].x), x2h = h22f2(xw[2].y);
        float2 x3l = h22f2(xw[3].x), x3h = h22f2(xw[3].y);
        acc.x += fmaf(w0, x0l.x, w1*x1l.x) + fmaf(w2, x2l.x, w3*x3l.x);
        acc.y += fmaf(w0, x0l.y, w1*x1l.y) + fmaf(w2, x2l.y, w3*x3l.y);
        acc.z += fmaf(w0, x0h.x, w1*x1h.x) + fmaf(w2, x2h.x, w3*x3h.x);
        acc.w += fmaf(w0, x0h.y, w1*x1h.y) + fmaf(w2, x2h.y, w3*x3h.y);
    }
    for (; e < e1; e++) {
        int p0 = __ldg(&adj[e]);
        unsigned src = (unsigned)p0 & 0xFFFFFu;
        unsigned t   = (unsigned)p0 >> 20;
        uint2 xw = ldnc2u(&xlh[src*64u + lane2]);
        uint2 rw = *(const uint2*)&relh[t*64u + lane2];
        __half2 m0 = __hadd2(u2h(xw.x), __hadd2(hxr0, u2h(rw.x)));
        __half2 m1 = __hadd2(u2h(xw.y), __hadd2(hxr1, u2h(rw.y)));
        __half2 l0 = __hfma2(m0, C06, __hmul2(__habs2(m0), C04));
        __half2 l1 = __hfma2(m1, C06, __hmul2(__habs2(m1), C04));
        __half2 dh = __hfma2(l1, hatt1, __hmul2(l0, hatt0));
        float2 df = __half22float2(dh);
        float d0 = df.x + df.y;
        d0 += __shfl_xor_sync(0xffffffffu, d0, 1);
        d0 += __shfl_xor_sync(0xffffffffu, d0, 2);
        d0 += __shfl_xor_sync(0xffffffffu, d0, 4);
        float w0 = __expf(d0);
        s += w0;
        float2 xl = h22f2(xw.x), xhp = h22f2(xw.y);
        acc.x = fmaf(w0, xl.x, acc.x);
        acc.y = fmaf(w0, xl.y, acc.y);
        acc.z = fmaf(w0, xhp.x, acc.z);
        acc.w = fmaf(w0, xhp.y, acc.w);
    }

    float inv = (s > 0.f) ? (1.f / s) : 0.f;
    float4 bj = *(const float4*)&bias[c0];
    float4 r;
    r.x = fmaf(acc.x, inv, bj.x);
    r.y = fmaf(acc.y, inv, bj.y);
    r.z = fmaf(acc.z, inv, bj.z);
    r.w = fmaf(acc.w, inv, bj.w);
    if (do_elu) {
        r.x = (r.x > 0.f) ? r.x : (__expf(r.x) - 1.f);
        r.y = (r.y > 0.f) ? r.y : (__expf(r.y) - 1.f);
        r.z = (r.z > 0.f) ? r.z : (__expf(r.z) - 1.f);
        r.w = (r.w > 0.f) ? r.w : (__expf(r.w) - 1.f);
    }
    if (xh) {
        uint2 w = make_uint2(f2h2(r.x, r.y), f2h2(r.z, r.w));
        *(uint2*)&xh[(size_t)warp*64 + lane*2] = w;
    } else {
        *(float4*)&out[warp*D + c0] = r;
    }
}

// ---------------- launch ----------------
extern "C" void kernel_launch(void* const* d_in, const int* in_sizes, int n_in,
                              void* d_out, int out_size) {
    const int*   entity = (const int*)  d_in[0];
    const int*   eidx   = (const int*)  d_in[1];
    const int*   etype  = (const int*)  d_in[2];
    const float* nf     = (const float*)d_in[3];
    const float* rel    = (const float*)d_in[4];
    const float* pw     = (const float*)d_in[5];
    const float* pb     = (const float*)d_in[6];
    const float* wl     = (const float*)d_in[7];
    const float* bl     = (const float*)d_in[8];
    const float* wr     = (const float*)d_in[9];
    const float* brr    = (const float*)d_in[10];
    const float* we     = (const float*)d_in[11];
    const float* att    = (const float*)d_in[12];
    const float* bias   = (const float*)d_in[13];
    float* out = (float*)d_out;

    int n  = in_sizes[0];
    int e  = in_sizes[2];
    int Rn = in_sizes[4] / D;
    int F  = in_sizes[3] / n;
    const int* srcp = eidx;
    const int* dstp = eidx + e;

    float *pxr;
    uint32_t *pxlh, *pbst, *pbpj, *pxh, *prelh;
    int *prow, *pwoff, *padj, *ppart;
    cudaGetSymbolAddress((void**)&pxlh,  g_xlh);
    cudaGetSymbolAddress((void**)&pxr,   g_xr);
    cudaGetSymbolAddress((void**)&pxh,   g_xh);
    cudaGetSymbolAddress((void**)&prelh, g_relh);
    cudaGetSymbolAddress((void**)&pbst,  g_bstage);
    cudaGetSymbolAddress((void**)&pbpj,  g_bproj);
    cudaGetSymbolAddress((void**)&prow,  g_rowptr);
    cudaGetSymbolAddress((void**)&pwoff, g_woff);
    cudaGetSymbolAddress((void**)&padj,  g_adj);
    cudaGetSymbolAddress((void**)&ppart, g_partials);

    int nsm = 148;
    cudaDeviceGetAttribute(&nsm, cudaDevAttrMultiProcessorCount, 0);

    cudaFuncSetAttribute(proj_mma_kernel, cudaFuncAttributeMaxDynamicSharedMemorySize, PM_SMEM);
    cudaFuncSetAttribute(gemm_dual_mma_kernel, cudaFuncAttributeMaxDynamicSharedMemorySize, MMA_SMEM);

    int nTiles = (n + 63) / 64;
    int projGrid = (nTiles < 2*nsm) ? nTiles : 2*nsm;
    int dualGrid = (nTiles < 2*nsm) ? nTiles : 2*nsm;
    int aggBlocks = (n*32 + 255) / 256;
    int nb = (n + 1023) / 1024;

    cudaMemsetAsync(pwoff, 0, (size_t)n * sizeof(int));
    prep_bp_kernel<<<128, 160>>>(pw, pbpj, F);
    prep_b_kernel<<<dim3(256, LAYERS), 64>>>(wl, wr, pbst);
    proj_mma_kernel<<<projGrid, 256, PM_SMEM>>>(nf, entity, pbpj, pb, pxh, n, F, nTiles);
    gemm_dual_mma_kernel<<<dualGrid, 256, MMA_SMEM>>>(pxh, pbst, bl, brr,
                                                      pxlh, pxr, n, nTiles);
    relproj_kernel<<<dim3((Rn + 3)/4, LAYERS), 64>>>(rel, we, prelh, Rn);
    hist_kernel<<<(e+255)/256, 256>>>(dstp, pwoff, e);
    scan1_kernel<<<nb, 1024>>>(pwoff, prow, ppart, n);
    scan2_kernel<<<1, 128>>>(ppart, prow, nb, n, e);
    scan3_kernel<<<(n+255)/256, 256>>>(prow, ppart, pwoff, n);
    scatter_kernel<<<(e+255)/256, 256>>>(srcp, dstp, etype, pwoff, padj, e);

    // layer 0 aggregation -> fp16 x image (feeds dual L1)
    gat_agg_kernel<<<aggBlocks, 256>>>(pxlh, pxr, prow, padj, prelh, att, bias,
                                       out, pxh, n, 1);

    // layer 1
    gemm_dual_mma_kernel<<<dualGrid, 256, MMA_SMEM>>>(pxh, pbst + 16384, bl + D, brr + D,
                                                      pxlh, pxr, n, nTiles);
    gat_agg_kernel<<<aggBlocks, 256>>>(pxlh, pxr, prow, padj, prelh + Rn*64, att + D, bias + D,
                                       out, (uint32_t*)nullptr, n, 0);
}